// round 2
// baseline (speedup 1.0000x reference)
#include <cuda_runtime.h>
#include <cuda_bf16.h>

// ----------------------------------------------------------------------------
// Extract-high-freq via db4 wavelet, reduced algebraically to:
//     out = 2*x - IDWT2_lowpass_only( DWT2_lowpass_only(x) )
// (perfect reconstruction => full pipeline with detail subbands scaled by 2
//  equals 2x minus the LL-only reconstruction).
// 4 separable, memory-bound kernels. fp32 throughout.
// ----------------------------------------------------------------------------

static constexpr int N  = 512;  // image side
static constexpr int M  = 259;  // (512 + 8 - 1) / 2  (pywt dwt output length)
static constexpr int MS = 260;  // padded stride for decimated dim (16B align)
static constexpr int BATCH_MAX = 96;  // 32 * 3

// Scratch (allocation-free rule: __device__ globals).
__device__ float g_A [BATCH_MAX * N * MS];  // row-lowpassed; reused as K3 output
__device__ float g_LL[BATCH_MAX * M * MS];  // LL subband

// db4 dec_lo filter
__constant__ float c_lo[8] = {
    -0.010597401784997278f,  0.032883011666982945f,
     0.030841381835986965f, -0.18703481171888114f,
    -0.02798376941698385f,   0.6308807679295904f,
     0.7148465705525415f,    0.23037781330885523f
};

__device__ __forceinline__ int refl(int i, int n) {
    // pywt 'symmetric': ...x1 x0 | x0 x1 ... x_{n-1} | x_{n-1} x_{n-2}...
    if (i < 0)  i = -1 - i;
    if (i >= n) i = 2 * n - 1 - i;
    return i;
}

// K1: forward lowpass along rows. One CTA per 512-float row.
__global__ void k_fwd_rows(const float* __restrict__ x, float* __restrict__ A) {
    __shared__ float s[N];
    const int row = blockIdx.x;                 // b*512 + r
    const float* xr = x + (size_t)row * N;
    const int tid = threadIdx.x;                // 256 threads
    s[tid]       = xr[tid];
    s[tid + 256] = xr[tid + 256];
    __syncthreads();
    float* Ar = A + (size_t)row * MS;
#pragma unroll
    for (int jj = 0; jj < 2; jj++) {
        const int j = tid + jj * 256;
        if (j < M) {
            const int base = 2 * j + 1;
            float acc = 0.f;
#pragma unroll
            for (int m = 0; m < 8; m++)
                acc += c_lo[m] * s[refl(base - m, N)];
            Ar[j] = acc;
        }
    }
}

// K2: forward lowpass along columns of A -> LL.
// grid: x = ceil(M/256) over j, y = batch * M over (b, i). Coalesced in j.
__global__ void k_fwd_cols(const float* __restrict__ A, float* __restrict__ LL) {
    const int j = blockIdx.x * blockDim.x + threadIdx.x;
    if (j >= M) return;
    const int r = blockIdx.y;                   // b * M + i
    const int i = r - (r / M) * M;
    const int b = r / M;
    const float* Ab = A + (size_t)b * N * MS + j;
    const int base = 2 * i + 1;
    float acc = 0.f;
#pragma unroll
    for (int m = 0; m < 8; m++)
        acc += c_lo[m] * Ab[(size_t)refl(base - m, N) * MS];
    LL[(size_t)r * MS + j] = acc;
}

// K3: inverse (upsample + rec_lo) along columns: LL -> B (stored in g_A).
// even s: taps d7,d5,d3,d1 at rows h+3..h ; odd s: d6,d4,d2,d0. h = s>>1.
// grid: x over j, y = batch * N over (b, s).
__global__ void k_inv_cols(const float* __restrict__ LL, float* __restrict__ B) {
    const int j = blockIdx.x * blockDim.x + threadIdx.x;
    if (j >= M) return;
    const int r = blockIdx.y;                   // b * N + s
    const int s = r & (N - 1);
    const int b = r >> 9;
    const int h = s >> 1;
    const float* Lb = LL + ((size_t)b * M + h) * MS + j;
    float acc;
    if ((s & 1) == 0)
        acc = c_lo[7] * Lb[3 * MS] + c_lo[5] * Lb[2 * MS]
            + c_lo[3] * Lb[MS]     + c_lo[1] * Lb[0];
    else
        acc = c_lo[6] * Lb[3 * MS] + c_lo[4] * Lb[2 * MS]
            + c_lo[2] * Lb[MS]     + c_lo[0] * Lb[0];
    B[(size_t)r * MS + j] = acc;
}

// K4: inverse along rows + combine: out = 2*x - rec. One CTA per row.
__global__ void k_inv_rows(const float* __restrict__ B, const float* __restrict__ x,
                           float* __restrict__ out) {
    __shared__ float sb[MS + 4];
    const int row = blockIdx.x;
    const float* Br = B + (size_t)row * MS;
    const int tid = threadIdx.x;                // 256 threads
    if (tid < M)       sb[tid]       = Br[tid];
    if (tid + 256 < M) sb[tid + 256] = Br[tid + 256];
    __syncthreads();
    const float* xr   = x   + (size_t)row * N;
    float*       outr = out + (size_t)row * N;
#pragma unroll
    for (int ss = 0; ss < 2; ss++) {
        const int s = tid + ss * 256;
        const int h = s >> 1;
        float acc;
        if ((s & 1) == 0)
            acc = c_lo[7] * sb[h + 3] + c_lo[5] * sb[h + 2]
                + c_lo[3] * sb[h + 1] + c_lo[1] * sb[h];
        else
            acc = c_lo[6] * sb[h + 3] + c_lo[4] * sb[h + 2]
                + c_lo[2] * sb[h + 1] + c_lo[0] * sb[h];
        outr[s] = 2.0f * xr[s] - acc;
    }
}

extern "C" void kernel_launch(void* const* d_in, const int* in_sizes, int n_in,
                              void* d_out, int out_size) {
    const float* x = (const float*)d_in[0];
    float* out = (float*)d_out;

    const int total_in = in_sizes[0];           // batch * 512 * 512
    const int nrows = total_in / N;             // batch * 512
    const int batch = nrows / N;                // 96

    float *A, *LL;
    cudaGetSymbolAddress((void**)&A,  g_A);
    cudaGetSymbolAddress((void**)&LL, g_LL);

    const dim3 blk(256);

    // K1: one block per image row.
    k_fwd_rows<<<nrows, blk>>>(x, A);

    // K2: 2D grid over (j ; b*M + i).
    k_fwd_cols<<<dim3((M + 255) / 256, batch * M), blk>>>(A, LL);

    // K3: 2D grid over (j ; b*N + s); writes back into g_A.
    k_inv_cols<<<dim3((M + 255) / 256, batch * N), blk>>>(LL, A);

    // K4: one block per output row; combines with input.
    k_inv_rows<<<nrows, blk>>>(A, x, out);
}

// round 4
// speedup vs baseline: 1.8133x; 1.8133x over previous
#include <cuda_runtime.h>
#include <cuda_bf16.h>

// ----------------------------------------------------------------------------
// out = 2*x - IDWT2_lowpass_only( DWT2_lowpass_only(x) )   (db4, pywt symmetric)
// Fused into 2 tiled kernels:
//   k_fwd: x -> LL     (row lowpass into smem, column lowpass out)
//   k_inv: LL,x -> out (column inverse into smem, row inverse + combine, f4)
// ----------------------------------------------------------------------------

static constexpr int N  = 512;
static constexpr int M  = 259;   // (512 + 8 - 1) / 2
static constexpr int MS = 260;   // padded LL stride
static constexpr int BATCH_MAX = 96;

// Forward tile
static constexpr int TI = 65, TJ = 65;
static constexpr int RT = 2 * TI + 7;    // 137 row-filtered rows needed
// Inverse tile (smem: 35*68*4 + 64*68*4 = 26.9 KB < 48 KB static limit)
static constexpr int TS = 64, TU = 128;
static constexpr int PT = TS / 2 + 3;    // 35 LL rows needed
static constexpr int QT = TU / 2 + 3;    // 67 LL cols needed
static constexpr int QS = 68;            // padded smem stride

__device__ float g_LL[BATCH_MAX * M * MS];   // 25.9 MB scratch

__constant__ float c_lo[8] = {
    -0.010597401784997278f,  0.032883011666982945f,
     0.030841381835986965f, -0.18703481171888114f,
    -0.02798376941698385f,   0.6308807679295904f,
     0.7148465705525415f,    0.23037781330885523f
};

__device__ __forceinline__ int refl(int i, int n) {
    if (i < 0)  i = -1 - i;
    if (i >= n) i = 2 * n - 1 - i;
    return i;
}

// ---------------------------------------------------------------------------
// Forward: one CTA per (b, 65x65 LL tile).
// Phase 1: As[rr][jj] = row-lowpass of x at actual row refl(r0+rr), col j0+jj.
// Phase 2: LL[i][j] = sum_m lo[m] * As[(2i+1-m)-r0][jj]  (reflection folded
//          into slot contents, so slot math is linear).
// ---------------------------------------------------------------------------
__global__ __launch_bounds__(256) void k_fwd(const float* __restrict__ x,
                                             float* __restrict__ LL) {
    __shared__ float As[RT][TJ];             // 35.6 KB
    const int b  = blockIdx.z;
    const int i0 = blockIdx.y * TI;
    const int j0 = blockIdx.x * TJ;
    const int r0 = 2 * i0 - 6;
    const float* xb = x + (size_t)b * N * N;

    for (int t = threadIdx.x; t < RT * TJ; t += 256) {
        const int rr = t / TJ;
        const int jj = t - rr * TJ;
        const int r  = refl(r0 + rr, N);
        const float* xr = xb + (size_t)r * N;
        const int base = 2 * (j0 + jj) + 1;
        float acc = 0.f;
        if (base >= 7 && base < N) {         // fast interior path
#pragma unroll
            for (int m = 0; m < 8; m++)
                acc += c_lo[m] * xr[base - m];
        } else {
#pragma unroll
            for (int m = 0; m < 8; m++)
                acc += c_lo[m] * xr[refl(base - m, N)];
        }
        As[rr][jj] = acc;
    }
    __syncthreads();

    for (int t = threadIdx.x; t < TI * TJ; t += 256) {
        const int ii = t / TJ;
        const int jj = t - ii * TJ;
        const int i = i0 + ii, j = j0 + jj;
        if (i < M && j < M) {
            const int qb = 2 * i + 1 - r0;   // slot for m=0 (<= 135 < RT)
            float acc = 0.f;
#pragma unroll
            for (int m = 0; m < 8; m++)
                acc += c_lo[m] * As[qb - m][jj];
            LL[((size_t)b * M + i) * MS + j] = acc;
        }
    }
}

// ---------------------------------------------------------------------------
// Inverse: one CTA per (b, 64x128 out tile). LL tap indices provably in
// range (p0+pp <= 254+34 < 259, q0+qq <= 192+66 < 259): no guards.
// ---------------------------------------------------------------------------
__global__ __launch_bounds__(256) void k_inv(const float* __restrict__ LL,
                                             const float* __restrict__ x,
                                             float* __restrict__ out) {
    __shared__ float Ls[PT][QS];             // 9.5 KB
    __shared__ float Bs[TS][QS];             // 17.4 KB
    const int b  = blockIdx.z;
    const int s0 = blockIdx.y * TS;
    const int u0 = blockIdx.x * TU;
    const int p0 = s0 >> 1, q0 = u0 >> 1;

    const float* Lb = LL + ((size_t)b * M + p0) * MS + q0;
    for (int t = threadIdx.x; t < PT * QT; t += 256) {
        const int pp = t / QT;
        const int qq = t - pp * QT;
        Ls[pp][qq] = Lb[(size_t)pp * MS + qq];
    }
    __syncthreads();

    // column inverse: Bs[ss][qq] over 64 x 67
    for (int t = threadIdx.x; t < TS * QT; t += 256) {
        const int ss = t / QT;
        const int qq = t - ss * QT;
        const int hh = ss >> 1;
        float acc;
        if ((ss & 1) == 0)
            acc = c_lo[7] * Ls[hh + 3][qq] + c_lo[5] * Ls[hh + 2][qq]
                + c_lo[3] * Ls[hh + 1][qq] + c_lo[1] * Ls[hh][qq];
        else
            acc = c_lo[6] * Ls[hh + 3][qq] + c_lo[4] * Ls[hh + 2][qq]
                + c_lo[2] * Ls[hh + 1][qq] + c_lo[0] * Ls[hh][qq];
        Bs[ss][qq] = acc;
    }
    __syncthreads();

    // row inverse + combine, float4 vectorized (u0 % 128 == 0 -> aligned)
    const float4* xb = (const float4*)(x   + ((size_t)b * N + s0) * N + u0);
    float4*       ob = (float4*)      (out + ((size_t)b * N + s0) * N + u0);
    constexpr int U4 = TU / 4;               // 32 float4 per row
    for (int t = threadIdx.x; t < TS * U4; t += 256) {
        const int ss = t >> 5;               // / U4
        const int v  = t & 31;
        const int k  = v * 2;                // hu for even lanes: k, k ; k+1, k+1
        const float* Br = Bs[ss];
        float4 r;
        r.x = c_lo[7] * Br[k + 3] + c_lo[5] * Br[k + 2]
            + c_lo[3] * Br[k + 1] + c_lo[1] * Br[k];
        r.y = c_lo[6] * Br[k + 3] + c_lo[4] * Br[k + 2]
            + c_lo[2] * Br[k + 1] + c_lo[0] * Br[k];
        r.z = c_lo[7] * Br[k + 4] + c_lo[5] * Br[k + 3]
            + c_lo[3] * Br[k + 2] + c_lo[1] * Br[k + 1];
        r.w = c_lo[6] * Br[k + 4] + c_lo[4] * Br[k + 3]
            + c_lo[2] * Br[k + 2] + c_lo[0] * Br[k + 1];
        const float4 xv = xb[(size_t)ss * (N / 4) + v];
        float4 o;
        o.x = 2.0f * xv.x - r.x;
        o.y = 2.0f * xv.y - r.y;
        o.z = 2.0f * xv.z - r.z;
        o.w = 2.0f * xv.w - r.w;
        ob[(size_t)ss * (N / 4) + v] = o;
    }
}

extern "C" void kernel_launch(void* const* d_in, const int* in_sizes, int n_in,
                              void* d_out, int out_size) {
    const float* x = (const float*)d_in[0];
    float* out = (float*)d_out;

    const int total_in = in_sizes[0];
    const int batch = total_in / (N * N);    // 96

    float* LL;
    cudaGetSymbolAddress((void**)&LL, g_LL);

    const dim3 blk(256);
    k_fwd<<<dim3((M + TJ - 1) / TJ, (M + TI - 1) / TI, batch), blk>>>(x, LL);
    k_inv<<<dim3(N / TU, N / TS, batch), blk>>>(LL, x, out);
}

// round 7
// speedup vs baseline: 1.8230x; 1.0053x over previous
#include <cuda_runtime.h>
#include <cuda_bf16.h>

// ----------------------------------------------------------------------------
// out = 2*x - IDWT2_lowpass_only( DWT2_lowpass_only(x) )   (db4, pywt symmetric)
//   k_fwd: x -> LL     (COLUMN lowpass first, coalesced float4; then row pass)
//   k_inv: LL,x -> out (column inverse into smem, row inverse + combine, f4)
// ----------------------------------------------------------------------------

static constexpr int N  = 512;
static constexpr int M  = 259;   // (512 + 8 - 1) / 2
static constexpr int MS = 260;   // padded LL stride (divisible by 4)
static constexpr int BATCH_MAX = 96;

// Forward tile: 64x64 LL outputs per CTA
static constexpr int TI = 64, TJ = 64;
static constexpr int CW = 2 * TJ + 8;    // 136 staged columns (f4-aligned span)
static constexpr int C4 = CW / 4;        // 34
// Inverse tile: 64x128 out per CTA
static constexpr int TS = 64, TU = 128;
static constexpr int PT = TS / 2 + 3;    // 35 LL rows
static constexpr int QT = TU / 2 + 3;    // 67 LL cols
static constexpr int QS = 68;            // padded smem stride (=17 float4)

__device__ float g_LL[BATCH_MAX * M * MS];   // 25.9 MB scratch

__constant__ float c_lo[8] = {
    -0.010597401784997278f,  0.032883011666982945f,
     0.030841381835986965f, -0.18703481171888114f,
    -0.02798376941698385f,   0.6308807679295904f,
     0.7148465705525415f,    0.23037781330885523f
};

__device__ __forceinline__ int refl(int i, int n) {
    if (i < 0)  i = -1 - i;
    if (i >= n) i = 2 * n - 1 - i;
    return i;
}

// ---------------------------------------------------------------------------
// Forward: one CTA per (b, 64x64 LL tile). Column pass first (coalesced),
// then row decimation from smem.
//   Cs[ii][cc] = sum_m lo[m] * x[refl(2*(i0+ii)+1-m)][refl(c0+cc)]
//   LL[i][j]   = sum_m lo[m] * Cs[ii][2*jj+9-m]     (slots 2..135, in range)
// c0 = 2*j0 - 8 is 4-float aligned (j0 = 64*bx), interior CTAs need no refl.
// ---------------------------------------------------------------------------
__global__ __launch_bounds__(256) void k_fwd(const float* __restrict__ x,
                                             float* __restrict__ LL) {
    __shared__ float Cs[TI][CW];             // 64*136*4 = 34.8 KB
    const int b  = blockIdx.z;
    const int i0 = blockIdx.y * TI;
    const int j0 = blockIdx.x * TJ;
    const int c0 = 2 * j0 - 8;
    const float* xb = x + (size_t)b * N * N;
    const int NI = min(TI, M - i0);          // LL rows this CTA produces

    if (c0 >= 0 && c0 + CW <= N) {
        // interior: aligned float4 loads, no column reflection
        for (int t = threadIdx.x; t < NI * C4; t += 256) {
            const int ii = t / C4;
            const int c4 = t - ii * C4;
            const int rb = 2 * (i0 + ii) + 1;
            float4 a = make_float4(0.f, 0.f, 0.f, 0.f);
#pragma unroll
            for (int m = 0; m < 8; m++) {
                const int r = refl(rb - m, N);
                const float4 v = *(const float4*)(xb + (size_t)r * N + c0 + 4 * c4);
                a.x += c_lo[m] * v.x; a.y += c_lo[m] * v.y;
                a.z += c_lo[m] * v.z; a.w += c_lo[m] * v.w;
            }
            *(float4*)&Cs[ii][4 * c4] = a;
        }
    } else {
        // edge CTAs: scalar path with column reflection; only stage the
        // columns actually consumed by phase 2.
        const int NC = min(CW, 2 * (M - j0) + 8);
        for (int t = threadIdx.x; t < NI * NC; t += 256) {
            const int ii = t / NC;
            const int cc = t - ii * NC;
            const int c  = refl(c0 + cc, N);
            const int rb = 2 * (i0 + ii) + 1;
            float a = 0.f;
#pragma unroll
            for (int m = 0; m < 8; m++)
                a += c_lo[m] * xb[(size_t)refl(rb - m, N) * N + c];
            Cs[ii][cc] = a;
        }
    }
    __syncthreads();

    for (int t = threadIdx.x; t < NI * TJ; t += 256) {
        const int ii = t >> 6;               // TJ = 64
        const int jj = t & 63;
        const int j  = j0 + jj;
        if (j < M) {
            float a = 0.f;
#pragma unroll
            for (int m = 0; m < 8; m++)
                a += c_lo[m] * Cs[ii][2 * jj + 9 - m];
            LL[((size_t)b * M + i0 + ii) * MS + j] = a;
        }
    }
}

// ---------------------------------------------------------------------------
// Inverse: one CTA per (b, 64x128 out tile). All LL tap indices provably in
// range; LL staging is float4 (QS = 17 float4 exactly, alignment proven).
// ---------------------------------------------------------------------------
__global__ __launch_bounds__(256) void k_inv(const float* __restrict__ LL,
                                             const float* __restrict__ x,
                                             float* __restrict__ out) {
    __shared__ float Ls[PT][QS];             // 9.5 KB
    __shared__ float Bs[TS][QS];             // 17.4 KB
    const int b  = blockIdx.z;
    const int s0 = blockIdx.y * TS;
    const int u0 = blockIdx.x * TU;
    const int p0 = s0 >> 1, q0 = u0 >> 1;

    // stage LL tile (float4): rows p0..p0+34, cols q0..q0+67 (within MS pad)
    const float4* Lb4 = (const float4*)(LL + ((size_t)b * M + p0) * MS + q0);
    for (int t = threadIdx.x; t < PT * (QS / 4); t += 256) {   // 35*17
        const int pp = t / 17;
        const int qf = t - pp * 17;
        *(float4*)&Ls[pp][4 * qf] = Lb4[(size_t)pp * (MS / 4) + qf];
    }
    __syncthreads();

    // column inverse, even/odd pair fused (shares the 4 taps)
    for (int t = threadIdx.x; t < (TS / 2) * QT; t += 256) {   // 32*67
        const int h  = t / QT;
        const int qq = t - h * QT;
        const float l0 = Ls[h][qq],     l1 = Ls[h + 1][qq];
        const float l2 = Ls[h + 2][qq], l3 = Ls[h + 3][qq];
        Bs[2 * h][qq]     = c_lo[7] * l3 + c_lo[5] * l2 + c_lo[3] * l1 + c_lo[1] * l0;
        Bs[2 * h + 1][qq] = c_lo[6] * l3 + c_lo[4] * l2 + c_lo[2] * l1 + c_lo[0] * l0;
    }
    __syncthreads();

    // row inverse + combine, float4 (u0 % 128 == 0 -> aligned)
    const float4* xb = (const float4*)(x   + ((size_t)b * N + s0) * N + u0);
    float4*       ob = (float4*)      (out + ((size_t)b * N + s0) * N + u0);
    constexpr int U4 = TU / 4;               // 32
    for (int t = threadIdx.x; t < TS * U4; t += 256) {
        const int ss = t >> 5;
        const int v  = t & 31;
        const int k  = v * 2;
        const float* Br = Bs[ss];
        const float b0 = Br[k], b1 = Br[k + 1], b2 = Br[k + 2];
        const float b3 = Br[k + 3], b4 = Br[k + 4];
        float4 r;
        r.x = c_lo[7] * b3 + c_lo[5] * b2 + c_lo[3] * b1 + c_lo[1] * b0;
        r.y = c_lo[6] * b3 + c_lo[4] * b2 + c_lo[2] * b1 + c_lo[0] * b0;
        r.z = c_lo[7] * b4 + c_lo[5] * b3 + c_lo[3] * b2 + c_lo[1] * b1;
        r.w = c_lo[6] * b4 + c_lo[4] * b3 + c_lo[2] * b2 + c_lo[0] * b1;
        const float4 xv = xb[(size_t)ss * (N / 4) + v];
        float4 o;
        o.x = 2.0f * xv.x - r.x;
        o.y = 2.0f * xv.y - r.y;
        o.z = 2.0f * xv.z - r.z;
        o.w = 2.0f * xv.w - r.w;
        ob[(size_t)ss * (N / 4) + v] = o;
    }
}

extern "C" void kernel_launch(void* const* d_in, const int* in_sizes, int n_in,
                              void* d_out, int out_size) {
    const float* x = (const float*)d_in[0];
    float* out = (float*)d_out;

    const int total_in = in_sizes[0];
    const int batch = total_in / (N * N);    // 96

    float* LL;
    cudaGetSymbolAddress((void**)&LL, g_LL);

    const dim3 blk(256);
    k_fwd<<<dim3((M + TJ - 1) / TJ, (M + TI - 1) / TI, batch), blk>>>(x, LL);
    k_inv<<<dim3(N / TU, N / TS, batch), blk>>>(LL, x, out);
}